// round 1
// baseline (speedup 1.0000x reference)
#include <cuda_runtime.h>
#include <math.h>

// Problem constants
constexpr int Bb = 256;   // batch
constexpr int Tt = 512;   // seq len
constexpr int Ii = 256;   // input size
constexpr int Hh = 512;   // hidden size
constexpr int Oo = 256;   // output size
constexpr int G4 = 4 * Hh; // 2048 = concatenated gate width (f,i,c,o)

// Scratch: precomputed input projections gx[t][b][gate*H + j], 1 GiB
__device__ float g_gx[(size_t)Tt * Bb * G4];
// Double-buffered hidden state + cell state
__device__ float g_h[2][Bb * Hh];
__device__ float g_c[Bb * Hh];

__device__ __forceinline__ float sigmoidf_(float x) {
    return 1.0f / (1.0f + expf(-x));
}

// ---------------------------------------------------------------------------
// Zero-init h0 and c0
// ---------------------------------------------------------------------------
__global__ void zero_hc() {
    int i = blockIdx.x * blockDim.x + threadIdx.x;
    if (i < Bb * Hh) {
        g_h[0][i] = 0.0f;
        g_c[i]    = 0.0f;
    }
}

// ---------------------------------------------------------------------------
// Phase 1: gx[m][n] = sum_k x_row(m)[k] * Wg[k][j] + bg[j]
//   m = t*B + b  (M = T*B = 131072), n = gate*H + j (N = 2048), K = I = 256
//   x_row(m) = inputs + (b*T + t)*I
// Tiling: BM=64, BN=64, BK=16, 256 threads, 4x4 per thread.
// ---------------------------------------------------------------------------
__global__ __launch_bounds__(256) void phase1_gemm(
    const float* __restrict__ x,
    const float* __restrict__ Wf, const float* __restrict__ Wi,
    const float* __restrict__ Wc, const float* __restrict__ Wo,
    const float* __restrict__ bf, const float* __restrict__ bi,
    const float* __restrict__ bc, const float* __restrict__ bo)
{
    __shared__ float As[16][64];   // [k][m]
    __shared__ float Bs[16][64];   // [k][n]

    const int tid = threadIdx.x;
    const int tx = tid & 15;       // n-quad index (cols tx*4 .. tx*4+3)
    const int ty = tid >> 4;       // m-quad index (rows ty*4 .. ty*4+3)

    const int m0 = blockIdx.y * 64;
    const int n0 = blockIdx.x * 64;
    const int gate = n0 >> 9;              // 64-wide tiles never straddle gates
    const int j0 = n0 & 511;

    const float* W    = (gate == 0) ? Wf : (gate == 1) ? Wi : (gate == 2) ? Wc : Wo;
    const float* bias = (gate == 0) ? bf : (gate == 1) ? bi : (gate == 2) ? bc : bo;

    // A-load mapping: 256 threads -> 64 rows x 4 k-quads
    const int ar = tid >> 2;       // row within tile 0..63
    const int aq = tid & 3;        // k-quad 0..3
    const int gm = m0 + ar;
    const int tstep = gm >> 8;     // m / B
    const int brow  = gm & 255;    // m % B
    const float* arow = x + ((size_t)brow * Tt + tstep) * Ii;

    // B-load mapping: 256 threads -> 16 k-rows x 16 n-quads
    const int br = tid >> 4;       // k row 0..15
    const int bq = tid & 15;       // n-quad 0..15

    float acc[4][4] = {};

    for (int k0 = 0; k0 < Ii; k0 += 16) {
        float4 av = *(const float4*)(arow + k0 + aq * 4);
        As[aq * 4 + 0][ar] = av.x;
        As[aq * 4 + 1][ar] = av.y;
        As[aq * 4 + 2][ar] = av.z;
        As[aq * 4 + 3][ar] = av.w;

        float4 bv = *(const float4*)(W + (size_t)(k0 + br) * Hh + j0 + bq * 4);
        *(float4*)&Bs[br][bq * 4] = bv;
        __syncthreads();

#pragma unroll
        for (int kk = 0; kk < 16; kk++) {
            float4 a4 = *(const float4*)&As[kk][ty * 4];
            float4 b4 = *(const float4*)&Bs[kk][tx * 4];
            float am[4] = {a4.x, a4.y, a4.z, a4.w};
            float bn[4] = {b4.x, b4.y, b4.z, b4.w};
#pragma unroll
            for (int i = 0; i < 4; i++)
#pragma unroll
                for (int j = 0; j < 4; j++)
                    acc[i][j] += am[i] * bn[j];
        }
        __syncthreads();
    }

    float4 bb = *(const float4*)(bias + j0 + tx * 4);
    const float bv4[4] = {bb.x, bb.y, bb.z, bb.w};
#pragma unroll
    for (int i = 0; i < 4; i++) {
        const int m = m0 + ty * 4 + i;
        float4 o;
        o.x = acc[i][0] + bv4[0];
        o.y = acc[i][1] + bv4[1];
        o.z = acc[i][2] + bv4[2];
        o.w = acc[i][3] + bv4[3];
        *(float4*)&g_gx[(size_t)m * G4 + n0 + tx * 4] = o;
    }
}

// ---------------------------------------------------------------------------
// Recurrent step: for all (b, j):
//   pre_g[b][g][j] = gx[t][b][g*H+j] + sum_k h[b][k] * Wgh[k][j]
//   f,i = sigmoid; g = tanh; c = f*c + i*g; h = o * tanh(c)
// CTA tile: 32 batch x 32 hidden-j, all 4 gates (GEMM as 32 x 128, K=512).
// 256 threads, 4x4 micro-tile per thread.
// ---------------------------------------------------------------------------
__global__ __launch_bounds__(256) void lstm_step(
    int t,
    const float* __restrict__ Wfh, const float* __restrict__ Wih,
    const float* __restrict__ Wch, const float* __restrict__ Woh)
{
    __shared__ union SM {
        struct { float As[16][32]; float Bs[16][128]; } ab;  // GEMM tiles
        float Gs[4][32][32];                                  // gate exchange
    } sm;

    const float* __restrict__ hin  = g_h[t & 1];
    float* __restrict__ hout       = g_h[(t + 1) & 1];
    const float* __restrict__ gx   = g_gx + (size_t)t * Bb * G4;

    const int tid = threadIdx.x;
    const int b0 = blockIdx.y * 32;
    const int j0 = blockIdx.x * 32;

    const int tx = tid & 31;   // n-quad (cols tx*4..tx*4+3 of 128)
    const int ty = tid >> 5;   // m-quad (rows ty*4..ty*4+3 of 32)

    // A-load (first 128 threads): 32 rows x 4 k-quads
    const int arr = tid >> 2;                  // batch row 0..31
    const int aq  = tid & 3;                   // k-quad
    const float* aptr = hin + (size_t)(b0 + arr) * Hh + aq * 4;

    // B-load: each thread loads 2 float4s from the 16x128 weight tile
    // idx = tid*2 + s : kk = idx>>5 (k row), n4 = idx&31 (float4 col)
    const float* bptr[2];
    float* bdst[2];
#pragma unroll
    for (int s = 0; s < 2; s++) {
        const int idx = tid * 2 + s;
        const int kk = idx >> 5;
        const int n4 = idx & 31;
        const int gsel = n4 >> 3;
        const float* W = (gsel == 0) ? Wfh : (gsel == 1) ? Wih : (gsel == 2) ? Wch : Woh;
        bptr[s] = W + (size_t)kk * Hh + j0 + (n4 & 7) * 4;
        bdst[s] = &sm.ab.Bs[kk][n4 * 4];
    }

    float acc[4][4] = {};

    for (int k0 = 0; k0 < Hh; k0 += 16) {
        if (tid < 128) {
            float4 av = *(const float4*)(aptr + k0);
            sm.ab.As[aq * 4 + 0][arr] = av.x;
            sm.ab.As[aq * 4 + 1][arr] = av.y;
            sm.ab.As[aq * 4 + 2][arr] = av.z;
            sm.ab.As[aq * 4 + 3][arr] = av.w;
        }
#pragma unroll
        for (int s = 0; s < 2; s++) {
            float4 bv = *(const float4*)(bptr[s] + (size_t)k0 * Hh);
            *(float4*)bdst[s] = bv;
        }
        __syncthreads();
#pragma unroll
        for (int kk = 0; kk < 16; kk++) {
            float4 a4 = *(const float4*)&sm.ab.As[kk][ty * 4];
            float4 b4 = *(const float4*)&sm.ab.Bs[kk][tx * 4];
            float am[4] = {a4.x, a4.y, a4.z, a4.w};
            float bn[4] = {b4.x, b4.y, b4.z, b4.w};
#pragma unroll
            for (int i = 0; i < 4; i++)
#pragma unroll
                for (int j = 0; j < 4; j++)
                    acc[i][j] += am[i] * bn[j];
        }
        __syncthreads();
    }

    // Add gx and stage gates into shared for cross-gate exchange.
    const int gsel = tx >> 3;              // this thread's gate
    const int jc = (tx & 7) * 4;           // col within 32-wide j tile
#pragma unroll
    for (int i = 0; i < 4; i++) {
        const int m = ty * 4 + i;
        float4 gv = *(const float4*)(gx + (size_t)(b0 + m) * G4 + gsel * Hh + j0 + jc);
        float4 o;
        o.x = acc[i][0] + gv.x;
        o.y = acc[i][1] + gv.y;
        o.z = acc[i][2] + gv.z;
        o.w = acc[i][3] + gv.w;
        *(float4*)&sm.Gs[gsel][m][jc] = o;
    }
    __syncthreads();

    // Fused pointwise LSTM update: 1024 (b,j) elements / 256 threads = 4 each
#pragma unroll
    for (int q = 0; q < 4; q++) {
        const int e = tid + 256 * q;
        const int m = e >> 5;
        const int jj = e & 31;
        const float fg = sigmoidf_(sm.Gs[0][m][jj]);
        const float ig = sigmoidf_(sm.Gs[1][m][jj]);
        const float gg = tanhf(sm.Gs[2][m][jj]);
        const float og = sigmoidf_(sm.Gs[3][m][jj]);
        const size_t cidx = (size_t)(b0 + m) * Hh + j0 + jj;
        const float cn = fg * g_c[cidx] + ig * gg;
        g_c[cidx] = cn;
        hout[cidx] = og * tanhf(cn);
    }
}

// ---------------------------------------------------------------------------
// Output head: logits = h_last @ Wout + bout; log_softmax per row.
// One CTA per batch row; 256 threads = one output each.
// ---------------------------------------------------------------------------
__global__ __launch_bounds__(256) void final_head(
    const float* __restrict__ Wout, const float* __restrict__ bout,
    float* __restrict__ out)
{
    __shared__ float hs[Hh];
    __shared__ float red[256];

    const int b = blockIdx.x;
    const int o = threadIdx.x;
    const float* hrow = g_h[0] + (size_t)b * Hh;   // t=511 (odd) wrote buf 0

    for (int k = o; k < Hh; k += 256) hs[k] = hrow[k];
    __syncthreads();

    float acc = bout[o];
#pragma unroll 4
    for (int k = 0; k < Hh; k++)
        acc += hs[k] * Wout[(size_t)k * Oo + o];

    // max reduce
    red[o] = acc;
    __syncthreads();
    for (int s = 128; s > 0; s >>= 1) {
        if (o < s) red[o] = fmaxf(red[o], red[o + s]);
        __syncthreads();
    }
    const float mx = red[0];
    __syncthreads();

    // sum of exp
    red[o] = expf(acc - mx);
    __syncthreads();
    for (int s = 128; s > 0; s >>= 1) {
        if (o < s) red[o] += red[o + s];
        __syncthreads();
    }
    const float lse = logf(red[0]) + mx;
    out[(size_t)b * Oo + o] = acc - lse;
}

// ---------------------------------------------------------------------------
// kernel_launch: zero-init -> phase1 GEMM -> 512 fused steps -> head
// All plain launches on the default stream; graph-capturable; no allocs.
// ---------------------------------------------------------------------------
extern "C" void kernel_launch(void* const* d_in, const int* in_sizes, int n_in,
                              void* d_out, int out_size)
{
    const float* inputs = (const float*)d_in[0];
    const float* Wf = (const float*)d_in[1];
    const float* bf = (const float*)d_in[2];
    const float* Wi = (const float*)d_in[3];
    const float* bi = (const float*)d_in[4];
    const float* Wc = (const float*)d_in[5];
    const float* bc = (const float*)d_in[6];
    const float* Wo = (const float*)d_in[7];
    const float* bo = (const float*)d_in[8];
    const float* Wout = (const float*)d_in[9];
    const float* bout = (const float*)d_in[10];
    float* out = (float*)d_out;

    zero_hc<<<(Bb * Hh + 255) / 256, 256>>>();

    // Phase 1: M = T*B = 131072 rows, N = 2048 cols, 64x64 tiles
    phase1_gemm<<<dim3(G4 / 64, (Tt * Bb) / 64), 256>>>(
        inputs, Wf, Wi, Wc, Wo, bf, bi, bc, bo);

    // Recurrence: h-part weights start at row I of each (I+H, H) matrix
    const float* Wfh = Wf + (size_t)Ii * Hh;
    const float* Wih = Wi + (size_t)Ii * Hh;
    const float* Wch = Wc + (size_t)Ii * Hh;
    const float* Woh = Wo + (size_t)Ii * Hh;
    for (int t = 0; t < Tt; t++) {
        lstm_step<<<dim3(Hh / 32, Bb / 32), 256>>>(t, Wfh, Wih, Wch, Woh);
    }

    final_head<<<Bb, 256>>>(Wout, bout, out);
}

// round 3
// speedup vs baseline: 4.8742x; 4.8742x over previous
#include <cuda_runtime.h>
#include <cuda_fp16.h>
#include <math.h>
#include <stdint.h>

// Problem constants
constexpr int Bb = 256;    // batch
constexpr int Tt = 512;    // seq len
constexpr int Ii = 256;    // input size
constexpr int Hh = 512;    // hidden size
constexpr int Oo = 256;    // output size
constexpr int G4 = 4 * Hh; // 2048 packed gate width, n = j*4 + g (0=f,1=i,2=c,3=o)

// ---------------------------------------------------------------------------
// Device scratch (allocation-free rule workaround)
// ---------------------------------------------------------------------------
__device__ float  g_gx[(size_t)Tt * Bb * G4];   // 1 GiB: input projections, m = t*B+b
__device__ __half g_xh[(size_t)Tt * Bb * Ii];   // 64 MB: x fp16, [m][k]
__device__ __half g_Wxh[(size_t)G4 * Ii];       // W_x packed [n][k] fp16
__device__ __half g_Whh[(size_t)G4 * Hh];       // W_h packed [n][k] fp16
__device__ float  g_biasp[G4];                  // bias packed [n]
__device__ __half g_hh[2][Bb * Hh];             // double-buffered hidden (fp16)
__device__ float  g_c[Bb * Hh];                 // cell state (fp32)

// ---------------------------------------------------------------------------
// PTX helpers (all base PTX: valid at compute_103 virtual arch)
// ---------------------------------------------------------------------------
__device__ __forceinline__ uint32_t smem_u32(const void* p) {
    uint32_t a;
    asm("{ .reg .u64 t; cvta.to.shared.u64 t, %1; cvt.u32.u64 %0, t; }" : "=r"(a) : "l"(p));
    return a;
}
__device__ __forceinline__ void cp16(uint32_t dst, const void* src) {
    asm volatile("cp.async.cg.shared.global [%0], [%1], 16;" :: "r"(dst), "l"(src));
}
#define CP_COMMIT() asm volatile("cp.async.commit_group;" ::: "memory")
#define CP_WAIT(n)  asm volatile("cp.async.wait_group %0;" :: "n"(n) : "memory")

__device__ __forceinline__ void ldm_x4(uint32_t (&r)[4], uint32_t addr) {
    asm volatile("ldmatrix.sync.aligned.m8n8.x4.shared.b16 {%0,%1,%2,%3}, [%4];"
        : "=r"(r[0]), "=r"(r[1]), "=r"(r[2]), "=r"(r[3]) : "r"(addr));
}
__device__ __forceinline__ void mma16816(float (&c)[4], const uint32_t (&a)[4], const uint32_t* b) {
    asm volatile("mma.sync.aligned.m16n8k16.row.col.f32.f16.f16.f32 "
        "{%0,%1,%2,%3}, {%4,%5,%6,%7}, {%8,%9}, {%0,%1,%2,%3};"
        : "+f"(c[0]), "+f"(c[1]), "+f"(c[2]), "+f"(c[3])
        : "r"(a[0]), "r"(a[1]), "r"(a[2]), "r"(a[3]), "r"(b[0]), "r"(b[1]));
}

// Fast activations (err ~1e-7, well below fp16 noise)
__device__ __forceinline__ float ex2f(float x) { float y; asm("ex2.approx.f32 %0, %1;" : "=f"(y) : "f"(x)); return y; }
__device__ __forceinline__ float rcpf(float x) { float y; asm("rcp.approx.f32 %0, %1;" : "=f"(y) : "f"(x)); return y; }
__device__ __forceinline__ float sigf(float x)   { return rcpf(1.0f + ex2f(-1.4426950408889634f * x)); }
__device__ __forceinline__ float tanhf_(float x) { return __fmaf_rn(2.0f, sigf(2.0f * x), -1.0f); }

// SMEM tile geometry: rows padded to 72 halves (144 B) -> conflict-free ldmatrix
constexpr int RSTRIDE = 144;  // bytes per smem row (64 data halves + 8 pad)

// Per-lane ldmatrix address offsets (within a tile at row base 0, k base 0)
__device__ __forceinline__ uint32_t a_lane_off(int lane) {
    return (uint32_t)(((lane & 7) + ((lane >> 3) & 1) * 8) * RSTRIDE + (lane >> 4) * 16);
}
__device__ __forceinline__ uint32_t b_lane_off(int lane) {
    return (uint32_t)(((lane & 7) + ((lane >> 4) & 1) * 8) * RSTRIDE + ((lane >> 3) & 1) * 16);
}

// ---------------------------------------------------------------------------
// Packing
// ---------------------------------------------------------------------------
__global__ void pack_x(const float* __restrict__ x) {
    size_t e = ((size_t)blockIdx.x * blockDim.x + threadIdx.x) * 4;
    if (e >= (size_t)Tt * Bb * Ii) return;
    int    k  = (int)(e & 255);
    size_t md = e >> 8;
    int    b  = (int)(md & 255);
    int    t  = (int)(md >> 8);
    float4 v = *(const float4*)(x + ((size_t)b * Tt + t) * Ii + k);
    *(__half2*)(g_xh + e)     = __floats2half2_rn(v.x, v.y);
    *(__half2*)(g_xh + e + 2) = __floats2half2_rn(v.z, v.w);
}

__global__ void pack_w(const float* __restrict__ Wf, const float* __restrict__ bf,
                       const float* __restrict__ Wi, const float* __restrict__ bi,
                       const float* __restrict__ Wc, const float* __restrict__ bc,
                       const float* __restrict__ Wo, const float* __restrict__ bo) {
    int k = blockIdx.x;  // 0..767
    for (int n = threadIdx.x; n < G4; n += blockDim.x) {
        int g = n & 3, j = n >> 2;
        const float* W = (g == 0) ? Wf : (g == 1) ? Wi : (g == 2) ? Wc : Wo;
        float v = W[(size_t)k * Hh + j];
        if (k < Ii) g_Wxh[(size_t)n * Ii + k] = __float2half_rn(v);
        else        g_Whh[(size_t)n * Hh + (k - Ii)] = __float2half_rn(v);
        if (k == 0) {
            const float* bp = (g == 0) ? bf : (g == 1) ? bi : (g == 2) ? bc : bo;
            g_biasp[n] = bp[j];
        }
    }
}

__global__ void zero_hc() {
    int i = blockIdx.x * blockDim.x + threadIdx.x;
    if (i < Bb * Hh) {
        g_hh[0][i] = __float2half_rn(0.0f);
        g_c[i] = 0.0f;
    }
}

// ---------------------------------------------------------------------------
// Phase 1: gx[m][n] = sum_k xh[m][k] * Wxh[n][k] + bias[n]
//   CTA 64(M) x 128(N), 256 thr (8 warps = 2x4), K=256 in 4 cp.async stages.
// ---------------------------------------------------------------------------
constexpr uint32_t P1_A0 = 0,      P1_B0 = 9216;
constexpr uint32_t P1_A1 = 27648,  P1_B1 = 36864;
constexpr int P1_SMEM = 55296;

__global__ void __launch_bounds__(256) phase1_mma() {
    extern __shared__ __align__(128) char smem[];
    const uint32_t sb = smem_u32(smem);
    const int tid = threadIdx.x, lane = tid & 31, wid = tid >> 5;
    const int wm = wid >> 2, wn = wid & 3;
    const int n0 = blockIdx.x * 128;
    const int m0 = blockIdx.y * 64;

    const uint32_t aoff = a_lane_off(lane);
    const uint32_t boff = b_lane_off(lane);

    float acc[2][4][4] = {};

    auto load_stage = [&](int s, uint32_t Ab, uint32_t Bx) {
        const int kb0 = s * 64;
#pragma unroll
        for (int q = 0; q < 2; q++) {                       // A: 64 x 64h = 512 cp16
            int i = tid + q * 256, r = i >> 3, g = i & 7;
            cp16(sb + Ab + r * RSTRIDE + g * 16, g_xh + (size_t)(m0 + r) * Ii + kb0 + g * 8);
        }
#pragma unroll
        for (int q = 0; q < 4; q++) {                       // B: 128 x 64h = 1024 cp16
            int i = tid + q * 256, r = i >> 3, g = i & 7;
            cp16(sb + Bx + r * RSTRIDE + g * 16, g_Wxh + (size_t)(n0 + r) * Ii + kb0 + g * 8);
        }
        CP_COMMIT();
    };
    auto compute = [&](uint32_t Ab, uint32_t Bx) {
#pragma unroll
        for (int kb = 0; kb < 64; kb += 16) {
            uint32_t a[2][4], b[2][4];
#pragma unroll
            for (int mi = 0; mi < 2; mi++)
                ldm_x4(a[mi], sb + Ab + (wm * 32 + mi * 16) * RSTRIDE + kb * 2 + aoff);
#pragma unroll
            for (int bi = 0; bi < 2; bi++)
                ldm_x4(b[bi], sb + Bx + (wn * 32 + bi * 16) * RSTRIDE + kb * 2 + boff);
#pragma unroll
            for (int mi = 0; mi < 2; mi++)
#pragma unroll
                for (int ni = 0; ni < 4; ni++)
                    mma16816(acc[mi][ni], a[mi], &b[ni >> 1][(ni & 1) * 2]);
        }
    };

    load_stage(0, P1_A0, P1_B0);
#pragma unroll
    for (int s = 0; s < 4; s++) {
        if (s < 3) { load_stage(s + 1, (s & 1) ? P1_A0 : P1_A1, (s & 1) ? P1_B0 : P1_B1); CP_WAIT(1); }
        else       { CP_WAIT(0); }
        __syncthreads();
        compute((s & 1) ? P1_A1 : P1_A0, (s & 1) ? P1_B1 : P1_B0);
        __syncthreads();
    }

    // Epilogue: direct fp32 store with bias
    const int r0 = wm * 32 + (lane >> 2);
    const int c0 = wn * 32 + 2 * (lane & 3);
#pragma unroll
    for (int mi = 0; mi < 2; mi++) {
#pragma unroll
        for (int ni = 0; ni < 4; ni++) {
            const int n = n0 + c0 + ni * 8;
            const float2 bv = *(const float2*)&g_biasp[n];
            const int m = m0 + r0 + mi * 16;
            *(float2*)(g_gx + (size_t)m * G4 + n) =
                make_float2(acc[mi][ni][0] + bv.x, acc[mi][ni][1] + bv.y);
            *(float2*)(g_gx + (size_t)(m + 8) * G4 + n) =
                make_float2(acc[mi][ni][2] + bv.x, acc[mi][ni][3] + bv.y);
        }
    }
}

// ---------------------------------------------------------------------------
// Recurrent step: pre[b][n] = gx[t][b][n] + sum_k h[b][k] * Whh[n][k]
//   CTA 64(batch) x 64(n = 16 j x 4 gates), 128 thr (4 warps = 2x2),
//   K=512 in 8 stages. Fused smem-exchange + LSTM pointwise epilogue.
// ---------------------------------------------------------------------------
constexpr uint32_t ST_A0 = 0,     ST_B0 = 9216;
constexpr uint32_t ST_A1 = 18432, ST_B1 = 27648;
constexpr int ST_SMEM = 36864;
constexpr int CS_STRIDE = 68;   // Cs[64][68] f32 (lives in buffer-0 region)

__global__ void __launch_bounds__(128) step_mma(int t) {
    extern __shared__ __align__(128) char smem[];
    const uint32_t sb = smem_u32(smem);
    float* Cs = (float*)smem;   // overlaps stage buffer 0; used after all MMA
    const int tid = threadIdx.x, lane = tid & 31, wid = tid >> 5;
    const int wm = wid >> 1, wn = wid & 1;
    const int n0 = blockIdx.x * 64;
    const int b0 = blockIdx.y * 64;

    const __half* __restrict__ hin = g_hh[t & 1];
    __half* __restrict__ hout      = g_hh[(t + 1) & 1];

    const uint32_t aoff = a_lane_off(lane);
    const uint32_t boff = b_lane_off(lane);

    float acc[2][4][4] = {};

    auto load_stage = [&](int s, uint32_t Ab, uint32_t Bx) {
        const int kb0 = s * 64;
#pragma unroll
        for (int q = 0; q < 4; q++) {                       // A: 64 x 64h
            int i = tid + q * 128, r = i >> 3, g = i & 7;
            cp16(sb + Ab + r * RSTRIDE + g * 16, hin + (size_t)(b0 + r) * Hh + kb0 + g * 8);
        }
#pragma unroll
        for (int q = 0; q < 4; q++) {                       // B: 64 x 64h
            int i = tid + q * 128, r = i >> 3, g = i & 7;
            cp16(sb + Bx + r * RSTRIDE + g * 16, g_Whh + (size_t)(n0 + r) * Hh + kb0 + g * 8);
        }
        CP_COMMIT();
    };
    auto compute = [&](uint32_t Ab, uint32_t Bx) {
#pragma unroll
        for (int kb = 0; kb < 64; kb += 16) {
            uint32_t a[2][4], b[2][4];
#pragma unroll
            for (int mi = 0; mi < 2; mi++)
                ldm_x4(a[mi], sb + Ab + (wm * 32 + mi * 16) * RSTRIDE + kb * 2 + aoff);
#pragma unroll
            for (int bi = 0; bi < 2; bi++)
                ldm_x4(b[bi], sb + Bx + (wn * 32 + bi * 16) * RSTRIDE + kb * 2 + boff);
#pragma unroll
            for (int mi = 0; mi < 2; mi++)
#pragma unroll
                for (int ni = 0; ni < 4; ni++)
                    mma16816(acc[mi][ni], a[mi], &b[ni >> 1][(ni & 1) * 2]);
        }
    };

    load_stage(0, ST_A0, ST_B0);
#pragma unroll
    for (int s = 0; s < 8; s++) {
        if (s < 7) { load_stage(s + 1, (s & 1) ? ST_A0 : ST_A1, (s & 1) ? ST_B0 : ST_B1); CP_WAIT(1); }
        else       { CP_WAIT(0); }
        __syncthreads();
        compute((s & 1) ? ST_A1 : ST_A0, (s & 1) ? ST_B1 : ST_B0);
        __syncthreads();
    }
    // Last stage read buffer 1; Cs (buffer-0 region) is free to write now.

    const int r0 = wm * 32 + (lane >> 2);
    const int c0 = wn * 32 + 2 * (lane & 3);
#pragma unroll
    for (int mi = 0; mi < 2; mi++) {
#pragma unroll
        for (int ni = 0; ni < 4; ni++) {
            const int rr = r0 + mi * 16, cc = c0 + ni * 8;
            Cs[rr * CS_STRIDE + cc]           = acc[mi][ni][0];
            Cs[rr * CS_STRIDE + cc + 1]       = acc[mi][ni][1];
            Cs[(rr + 8) * CS_STRIDE + cc]     = acc[mi][ni][2];
            Cs[(rr + 8) * CS_STRIDE + cc + 1] = acc[mi][ni][3];
        }
    }
    __syncthreads();

    // Pointwise LSTM update: thread -> (row, half of j-tile)
    const int row = tid >> 1, jq = tid & 1;
    const int b = b0 + row;
    const float* gxr  = g_gx + ((size_t)t * Bb + b) * G4 + n0 + jq * 32;
    float*  crow = g_c + (size_t)b * Hh + (n0 >> 2) + jq * 8;
    __half* hrow = hout + (size_t)b * Hh + (n0 >> 2) + jq * 8;
    const float* cs = Cs + row * CS_STRIDE + jq * 32;

    float cv[8];
    *(float4*)&cv[0] = *(const float4*)(crow);
    *(float4*)&cv[4] = *(const float4*)(crow + 4);
    __half hb[8];
#pragma unroll
    for (int j = 0; j < 8; j++) {
        float4 pre = *(const float4*)(cs + j * 4);   // (f,i,c,o) partial W_h·h
        float4 gxv = *(const float4*)(gxr + j * 4);  // precomputed W_x·x + bias
        float fg = sigf(pre.x + gxv.x);
        float ig = sigf(pre.y + gxv.y);
        float gg = tanhf_(pre.z + gxv.z);
        float og = sigf(pre.w + gxv.w);
        float cn = fg * cv[j] + ig * gg;
        cv[j] = cn;
        hb[j] = __float2half_rn(og * tanhf_(cn));
    }
    *(float4*)(crow)     = *(float4*)&cv[0];
    *(float4*)(crow + 4) = *(float4*)&cv[4];
    *(uint4*)(hrow)      = *(uint4*)hb;
}

// ---------------------------------------------------------------------------
// Output head: logits = h_last @ Wout + bout; log_softmax per row.
// ---------------------------------------------------------------------------
__global__ __launch_bounds__(256) void final_head(
    const float* __restrict__ Wout, const float* __restrict__ bout,
    float* __restrict__ out)
{
    __shared__ float hs[Hh];
    __shared__ float red[256];

    const int b = blockIdx.x;
    const int o = threadIdx.x;
    const __half* hrow = g_hh[0] + (size_t)b * Hh;   // t=511 wrote buffer 0

    for (int k = o; k < Hh; k += 256) hs[k] = __half2float(hrow[k]);
    __syncthreads();

    float acc = bout[o];
#pragma unroll 4
    for (int k = 0; k < Hh; k++)
        acc += hs[k] * Wout[(size_t)k * Oo + o];

    red[o] = acc;
    __syncthreads();
    for (int s = 128; s > 0; s >>= 1) {
        if (o < s) red[o] = fmaxf(red[o], red[o + s]);
        __syncthreads();
    }
    const float mx = red[0];
    __syncthreads();

    red[o] = expf(acc - mx);
    __syncthreads();
    for (int s = 128; s > 0; s >>= 1) {
        if (o < s) red[o] += red[o + s];
        __syncthreads();
    }
    const float lse = logf(red[0]) + mx;
    out[(size_t)b * Oo + o] = acc - lse;
}

// ---------------------------------------------------------------------------
// kernel_launch
// ---------------------------------------------------------------------------
extern "C" void kernel_launch(void* const* d_in, const int* in_sizes, int n_in,
                              void* d_out, int out_size)
{
    const float* inputs = (const float*)d_in[0];
    const float* Wf = (const float*)d_in[1];
    const float* bf = (const float*)d_in[2];
    const float* Wi = (const float*)d_in[3];
    const float* bi = (const float*)d_in[4];
    const float* Wc = (const float*)d_in[5];
    const float* bc = (const float*)d_in[6];
    const float* Wo = (const float*)d_in[7];
    const float* bo = (const float*)d_in[8];
    const float* Wout = (const float*)d_in[9];
    const float* bout = (const float*)d_in[10];
    float* out = (float*)d_out;

    static bool attr_done = false;
    if (!attr_done) {
        cudaFuncSetAttribute(phase1_mma, cudaFuncAttributeMaxDynamicSharedMemorySize, P1_SMEM);
        cudaFuncSetAttribute(step_mma,   cudaFuncAttributeMaxDynamicSharedMemorySize, ST_SMEM);
        attr_done = true;
    }

    pack_x<<<(unsigned)((size_t)Tt * Bb * Ii / 4 / 256), 256>>>(inputs);
    pack_w<<<Ii + Hh, 256>>>(Wf, bf, Wi, bi, Wc, bc, Wo, bo);
    zero_hc<<<(Bb * Hh + 255) / 256, 256>>>();

    // Phase 1: M = 131072, N = 2048, K = 256
    phase1_mma<<<dim3(G4 / 128, (Tt * Bb) / 64), 256, P1_SMEM>>>();

    // Recurrence: 512 steps, 128 CTAs each
    for (int t = 0; t < Tt; t++) {
        step_mma<<<dim3(G4 / 4 / 16, Bb / 64), 128, ST_SMEM>>>(t);
    }

    final_head<<<Bb, 256>>>(Wout, bout, out);
}

// round 4
// speedup vs baseline: 6.4208x; 1.3173x over previous
#include <cuda_runtime.h>
#include <cuda_fp16.h>
#include <math.h>
#include <stdint.h>

// Problem constants
constexpr int Bb = 256;    // batch
constexpr int Tt = 512;    // seq len
constexpr int Ii = 256;    // input size
constexpr int Hh = 512;    // hidden size
constexpr int Oo = 256;    // output size
constexpr int G4 = 4 * Hh; // 2048 packed gate width, n = j*4 + g (0=f,1=i,2=c,3=o)

// ---------------------------------------------------------------------------
// Device scratch
// ---------------------------------------------------------------------------
__device__ __half g_gx[(size_t)Tt * Bb * G4];   // 512 MB: input projections fp16, m = t*B+b
__device__ __half g_xh[(size_t)Tt * Bb * Ii];   // 64 MB: x fp16, [m][k]
__device__ __half g_Wxh[(size_t)G4 * Ii];       // W_x packed [n][k] fp16
__device__ __half g_Whh[(size_t)G4 * Hh];       // W_h packed [n][k] fp16
__device__ float  g_biasp[G4];                  // bias packed [n]
__device__ __half g_hh[2][Bb * Hh];             // double-buffered hidden (fp16)
__device__ unsigned g_ctr;                      // grid barrier counter

// ---------------------------------------------------------------------------
// PTX helpers (base PTX only: valid at compute_103 virtual arch)
// ---------------------------------------------------------------------------
__device__ __forceinline__ uint32_t smem_u32(const void* p) {
    uint32_t a;
    asm("{ .reg .u64 t; cvta.to.shared.u64 t, %1; cvt.u32.u64 %0, t; }" : "=r"(a) : "l"(p));
    return a;
}
__device__ __forceinline__ void cp16(uint32_t dst, const void* src) {
    asm volatile("cp.async.cg.shared.global [%0], [%1], 16;" :: "r"(dst), "l"(src));
}
#define CP_COMMIT() asm volatile("cp.async.commit_group;" ::: "memory")
#define CP_WAIT(n)  asm volatile("cp.async.wait_group %0;" :: "n"(n) : "memory")

__device__ __forceinline__ void ldm_x4(uint32_t (&r)[4], uint32_t addr) {
    asm volatile("ldmatrix.sync.aligned.m8n8.x4.shared.b16 {%0,%1,%2,%3}, [%4];"
        : "=r"(r[0]), "=r"(r[1]), "=r"(r[2]), "=r"(r[3]) : "r"(addr));
}
__device__ __forceinline__ void mma16816(float (&c)[4], const uint32_t (&a)[4], const uint32_t* b) {
    asm volatile("mma.sync.aligned.m16n8k16.row.col.f32.f16.f16.f32 "
        "{%0,%1,%2,%3}, {%4,%5,%6,%7}, {%8,%9}, {%0,%1,%2,%3};"
        : "+f"(c[0]), "+f"(c[1]), "+f"(c[2]), "+f"(c[3])
        : "r"(a[0]), "r"(a[1]), "r"(a[2]), "r"(a[3]), "r"(b[0]), "r"(b[1]));
}

// Fast activations (err ~1e-7, below fp16 noise)
__device__ __forceinline__ float ex2f(float x) { float y; asm("ex2.approx.f32 %0, %1;" : "=f"(y) : "f"(x)); return y; }
__device__ __forceinline__ float rcpf(float x) { float y; asm("rcp.approx.f32 %0, %1;" : "=f"(y) : "f"(x)); return y; }
__device__ __forceinline__ float sigf(float x)   { return rcpf(1.0f + ex2f(-1.4426950408889634f * x)); }
__device__ __forceinline__ float tanhf_(float x) { return __fmaf_rn(2.0f, sigf(2.0f * x), -1.0f); }

// SMEM tile geometry: 64 data halves + 8 pad per row -> conflict-free ldmatrix
constexpr int RSTRIDE = 144;                 // bytes per smem row
constexpr int CHUNK_BYTES = 64 * RSTRIDE;    // one 64x64-half chunk = 9216 B

__device__ __forceinline__ uint32_t a_lane_off(int lane) {
    return (uint32_t)(((lane & 7) + ((lane >> 3) & 1) * 8) * RSTRIDE + (lane >> 4) * 16);
}
__device__ __forceinline__ uint32_t b_lane_off(int lane) {
    return (uint32_t)(((lane & 7) + ((lane >> 4) & 1) * 8) * RSTRIDE + ((lane >> 3) & 1) * 16);
}

// ---------------------------------------------------------------------------
// Packing
// ---------------------------------------------------------------------------
__global__ void pack_x(const float* __restrict__ x) {
    size_t e = ((size_t)blockIdx.x * blockDim.x + threadIdx.x) * 4;
    if (e >= (size_t)Tt * Bb * Ii) return;
    int    k  = (int)(e & 255);
    size_t md = e >> 8;
    int    b  = (int)(md & 255);
    int    t  = (int)(md >> 8);
    float4 v = *(const float4*)(x + ((size_t)b * Tt + t) * Ii + k);
    *(__half2*)(g_xh + e)     = __floats2half2_rn(v.x, v.y);
    *(__half2*)(g_xh + e + 2) = __floats2half2_rn(v.z, v.w);
}

__global__ void pack_w(const float* __restrict__ Wf, const float* __restrict__ bf,
                       const float* __restrict__ Wi, const float* __restrict__ bi,
                       const float* __restrict__ Wc, const float* __restrict__ bc,
                       const float* __restrict__ Wo, const float* __restrict__ bo) {
    int k = blockIdx.x;  // 0..767
    for (int n = threadIdx.x; n < G4; n += blockDim.x) {
        int g = n & 3, j = n >> 2;
        const float* W = (g == 0) ? Wf : (g == 1) ? Wi : (g == 2) ? Wc : Wo;
        float v = W[(size_t)k * Hh + j];
        if (k < Ii) g_Wxh[(size_t)n * Ii + k] = __float2half_rn(v);
        else        g_Whh[(size_t)n * Hh + (k - Ii)] = __float2half_rn(v);
        if (k == 0) {
            const float* bp = (g == 0) ? bf : (g == 1) ? bi : (g == 2) ? bc : bo;
            g_biasp[n] = bp[j];
        }
    }
}

__global__ void zero_state() {
    int i = blockIdx.x * blockDim.x + threadIdx.x;
    if (i == 0) g_ctr = 0;
    if (i < Bb * Hh) g_hh[0][i] = __float2half_rn(0.0f);
}

// ---------------------------------------------------------------------------
// Phase 1: gx[m][n] = fp16( sum_k xh[m][k] * Wxh[n][k] + bias[n] )
//   CTA 64(M) x 128(N), 256 thr (8 warps = 2x4), K=256 in 4 cp.async stages.
// ---------------------------------------------------------------------------
constexpr uint32_t P1_A0 = 0,      P1_B0 = 9216;
constexpr uint32_t P1_A1 = 27648,  P1_B1 = 36864;
constexpr int P1_SMEM = 55296;

__global__ void __launch_bounds__(256) phase1_mma() {
    extern __shared__ __align__(128) char smem[];
    const uint32_t sb = smem_u32(smem);
    const int tid = threadIdx.x, lane = tid & 31, wid = tid >> 5;
    const int wm = wid >> 2, wn = wid & 3;
    const int n0 = blockIdx.x * 128;
    const int m0 = blockIdx.y * 64;

    const uint32_t aoff = a_lane_off(lane);
    const uint32_t boff = b_lane_off(lane);

    float acc[2][4][4] = {};

    auto load_stage = [&](int s, uint32_t Ab, uint32_t Bx) {
        const int kb0 = s * 64;
#pragma unroll
        for (int q = 0; q < 2; q++) {
            int i = tid + q * 256, r = i >> 3, g = i & 7;
            cp16(sb + Ab + r * RSTRIDE + g * 16, g_xh + (size_t)(m0 + r) * Ii + kb0 + g * 8);
        }
#pragma unroll
        for (int q = 0; q < 4; q++) {
            int i = tid + q * 256, r = i >> 3, g = i & 7;
            cp16(sb + Bx + r * RSTRIDE + g * 16, g_Wxh + (size_t)(n0 + r) * Ii + kb0 + g * 8);
        }
        CP_COMMIT();
    };
    auto compute = [&](uint32_t Ab, uint32_t Bx) {
#pragma unroll
        for (int kb = 0; kb < 64; kb += 16) {
            uint32_t a[2][4], b[2][4];
#pragma unroll
            for (int mi = 0; mi < 2; mi++)
                ldm_x4(a[mi], sb + Ab + (wm * 32 + mi * 16) * RSTRIDE + kb * 2 + aoff);
#pragma unroll
            for (int bi = 0; bi < 2; bi++)
                ldm_x4(b[bi], sb + Bx + (wn * 32 + bi * 16) * RSTRIDE + kb * 2 + boff);
#pragma unroll
            for (int mi = 0; mi < 2; mi++)
#pragma unroll
                for (int ni = 0; ni < 4; ni++)
                    mma16816(acc[mi][ni], a[mi], &b[ni >> 1][(ni & 1) * 2]);
        }
    };

    load_stage(0, P1_A0, P1_B0);
#pragma unroll
    for (int s = 0; s < 4; s++) {
        if (s < 3) { load_stage(s + 1, (s & 1) ? P1_A0 : P1_A1, (s & 1) ? P1_B0 : P1_B1); CP_WAIT(1); }
        else       { CP_WAIT(0); }
        __syncthreads();
        compute((s & 1) ? P1_A1 : P1_A0, (s & 1) ? P1_B1 : P1_B0);
        __syncthreads();
    }

    // Epilogue: fp16 store with bias
    const int r0 = wm * 32 + (lane >> 2);
    const int c0 = wn * 32 + 2 * (lane & 3);
#pragma unroll
    for (int mi = 0; mi < 2; mi++) {
#pragma unroll
        for (int ni = 0; ni < 4; ni++) {
            const int n = n0 + c0 + ni * 8;
            const float2 bv = *(const float2*)&g_biasp[n];
            const int m = m0 + r0 + mi * 16;
            *(__half2*)(g_gx + (size_t)m * G4 + n) =
                __floats2half2_rn(acc[mi][ni][0] + bv.x, acc[mi][ni][1] + bv.y);
            *(__half2*)(g_gx + (size_t)(m + 8) * G4 + n) =
                __floats2half2_rn(acc[mi][ni][2] + bv.x, acc[mi][ni][3] + bv.y);
        }
    }
}

// ---------------------------------------------------------------------------
// Persistent recurrence: 128 CTAs (n-tiles x b-tiles), all 512 steps in one
// kernel. W_h tile resident in smem; c state in registers; grid spin barrier.
// ---------------------------------------------------------------------------
constexpr uint32_t PS_A  = 0;                       // A (h) chunks: 8 x 9216
constexpr uint32_t PS_B  = 8 * CHUNK_BYTES;         // B (Wh) resident: 8 x 9216
constexpr uint32_t PS_GX = 16 * CHUNK_BYTES;        // gx slice: 64 x 64 halves = 8192
constexpr uint32_t PS_CS = PS_GX + 8192;            // Cs exchange: 64 x 68 f32
constexpr int CS_STRIDE = 68;
constexpr int PS_SMEM = PS_CS + 64 * CS_STRIDE * 4; // 173056 B

__global__ void __launch_bounds__(128) lstm_persistent() {
    extern __shared__ __align__(128) char smem[];
    const uint32_t sb = smem_u32(smem);
    float*  Cs  = (float*)(smem + PS_CS);
    __half* gxs = (__half*)(smem + PS_GX);
    const int tid = threadIdx.x, lane = tid & 31, wid = tid >> 5;
    const int wm = wid >> 1, wn = wid & 1;
    const int n0 = blockIdx.x * 64;
    const int b0 = blockIdx.y * 64;
    const unsigned NCTA = gridDim.x * gridDim.y;   // 128

    const uint32_t aoff = a_lane_off(lane);
    const uint32_t boff = b_lane_off(lane);

    // Resident B: W_h tile 64(n) x 512(k), 8 chunks, loaded once.
#pragma unroll
    for (int c = 0; c < 8; c++) {
#pragma unroll
        for (int q = 0; q < 4; q++) {
            int i = tid + q * 128, r = i >> 3, g = i & 7;
            cp16(sb + PS_B + c * CHUNK_BYTES + r * RSTRIDE + g * 16,
                 g_Whh + (size_t)(n0 + r) * Hh + c * 64 + g * 8);
        }
    }
    CP_COMMIT();

    // Epilogue mapping: thread -> (batch row, half of 16-j tile); c in regs.
    const int erow = tid >> 1, ejq = tid & 1;
    const int eb = b0 + erow;
    float cv[8];
#pragma unroll
    for (int j = 0; j < 8; j++) cv[j] = 0.0f;

    CP_WAIT(0);
    __syncthreads();

    auto compute = [&](int kc, float (&acc)[2][4][4]) {
        const uint32_t Ab = sb + PS_A + kc * CHUNK_BYTES;
        const uint32_t Bx = sb + PS_B + kc * CHUNK_BYTES;
#pragma unroll
        for (int kb = 0; kb < 64; kb += 16) {
            uint32_t a[2][4], b[2][4];
#pragma unroll
            for (int mi = 0; mi < 2; mi++)
                ldm_x4(a[mi], Ab + (wm * 32 + mi * 16) * RSTRIDE + kb * 2 + aoff);
#pragma unroll
            for (int bi = 0; bi < 2; bi++)
                ldm_x4(b[bi], Bx + (wn * 32 + bi * 16) * RSTRIDE + kb * 2 + boff);
#pragma unroll
            for (int mi = 0; mi < 2; mi++)
#pragma unroll
                for (int ni = 0; ni < 4; ni++)
                    mma16816(acc[mi][ni], a[mi], &b[ni >> 1][(ni & 1) * 2]);
        }
    };

    for (int t = 0; t < Tt; t++) {
        const __half* __restrict__ hin  = g_hh[t & 1];
        __half* __restrict__ hout       = g_hh[(t + 1) & 1];

        // Group 0: gx slice + A chunks 0..3
        {
            const __half* gsrc = g_gx + ((size_t)t * Bb + b0) * G4 + n0;
#pragma unroll
            for (int q = 0; q < 4; q++) {
                int i = tid + q * 128, r = i >> 3, g = i & 7;
                cp16(sb + PS_GX + r * 128 + g * 16, gsrc + (size_t)r * G4 + g * 8);
            }
#pragma unroll
            for (int c = 0; c < 4; c++) {
#pragma unroll
                for (int q = 0; q < 4; q++) {
                    int i = tid + q * 128, r = i >> 3, g = i & 7;
                    cp16(sb + PS_A + c * CHUNK_BYTES + r * RSTRIDE + g * 16,
                         hin + (size_t)(b0 + r) * Hh + c * 64 + g * 8);
                }
            }
            CP_COMMIT();
        }
        // Group 1: A chunks 4..7
#pragma unroll
        for (int c = 4; c < 8; c++) {
#pragma unroll
            for (int q = 0; q < 4; q++) {
                int i = tid + q * 128, r = i >> 3, g = i & 7;
                cp16(sb + PS_A + c * CHUNK_BYTES + r * RSTRIDE + g * 16,
                     hin + (size_t)(b0 + r) * Hh + c * 64 + g * 8);
            }
        }
        CP_COMMIT();

        float acc[2][4][4] = {};
        CP_WAIT(1);
        __syncthreads();
#pragma unroll
        for (int c = 0; c < 4; c++) compute(c, acc);
        CP_WAIT(0);
        __syncthreads();
#pragma unroll
        for (int c = 4; c < 8; c++) compute(c, acc);

        // Exchange accumulators through smem (row-major Cs)
        const int r0 = wm * 32 + (lane >> 2);
        const int c0 = wn * 32 + 2 * (lane & 3);
#pragma unroll
        for (int mi = 0; mi < 2; mi++) {
#pragma unroll
            for (int ni = 0; ni < 4; ni++) {
                const int rr = r0 + mi * 16, cc = c0 + ni * 8;
                Cs[rr * CS_STRIDE + cc]           = acc[mi][ni][0];
                Cs[rr * CS_STRIDE + cc + 1]       = acc[mi][ni][1];
                Cs[(rr + 8) * CS_STRIDE + cc]     = acc[mi][ni][2];
                Cs[(rr + 8) * CS_STRIDE + cc + 1] = acc[mi][ni][3];
            }
        }
        __syncthreads();

        // Pointwise LSTM update (c in registers)
        {
            const float* cs = Cs + erow * CS_STRIDE + ejq * 32;
            const __half* gr = gxs + erow * 64 + ejq * 32;
            __half hb[8];
#pragma unroll
            for (int j = 0; j < 8; j++) {
                float4 pre = *(const float4*)(cs + j * 4);      // W_h·h partial (f,i,c,o)
                float2 g01 = __half22float2(*(const __half2*)(gr + j * 4));
                float2 g23 = __half22float2(*(const __half2*)(gr + j * 4 + 2));
                float fg = sigf(pre.x + g01.x);
                float ig = sigf(pre.y + g01.y);
                float gg = tanhf_(pre.z + g23.x);
                float og = sigf(pre.w + g23.y);
                float cn = fg * cv[j] + ig * gg;
                cv[j] = cn;
                hb[j] = __float2half_rn(og * tanhf_(cn));
            }
            *(uint4*)(hout + (size_t)eb * Hh + (n0 >> 2) + ejq * 8) = *(uint4*)hb;
        }

        // Grid barrier: h(t+1) visible to all before next step
        __threadfence();
        __syncthreads();
        if (tid == 0) {
            atomicAdd(&g_ctr, 1u);
            const unsigned target = (unsigned)(t + 1) * NCTA;
            while (*(volatile unsigned*)&g_ctr < target) __nanosleep(64);
        }
        __syncthreads();
    }
}

// ---------------------------------------------------------------------------
// Output head: logits = h_last @ Wout + bout; log_softmax per row.
// ---------------------------------------------------------------------------
__global__ __launch_bounds__(256) void final_head(
    const float* __restrict__ Wout, const float* __restrict__ bout,
    float* __restrict__ out)
{
    __shared__ float hs[Hh];
    __shared__ float red[256];

    const int b = blockIdx.x;
    const int o = threadIdx.x;
    const __half* hrow = g_hh[0] + (size_t)b * Hh;   // t=511 wrote buffer 0

    for (int k = o; k < Hh; k += 256) hs[k] = __half2float(hrow[k]);
    __syncthreads();

    float acc = bout[o];
#pragma unroll 4
    for (int k = 0; k < Hh; k++)
        acc += hs[k] * Wout[(size_t)k * Oo + o];

    red[o] = acc;
    __syncthreads();
    for (int s = 128; s > 0; s >>= 1) {
        if (o < s) red[o] = fmaxf(red[o], red[o + s]);
        __syncthreads();
    }
    const float mx = red[0];
    __syncthreads();

    red[o] = expf(acc - mx);
    __syncthreads();
    for (int s = 128; s > 0; s >>= 1) {
        if (o < s) red[o] += red[o + s];
        __syncthreads();
    }
    const float lse = logf(red[0]) + mx;
    out[(size_t)b * Oo + o] = acc - lse;
}

// ---------------------------------------------------------------------------
// kernel_launch
// ---------------------------------------------------------------------------
extern "C" void kernel_launch(void* const* d_in, const int* in_sizes, int n_in,
                              void* d_out, int out_size)
{
    const float* inputs = (const float*)d_in[0];
    const float* Wf = (const float*)d_in[1];
    const float* bf = (const float*)d_in[2];
    const float* Wi = (const float*)d_in[3];
    const float* bi = (const float*)d_in[4];
    const float* Wc = (const float*)d_in[5];
    const float* bc = (const float*)d_in[6];
    const float* Wo = (const float*)d_in[7];
    const float* bo = (const float*)d_in[8];
    const float* Wout = (const float*)d_in[9];
    const float* bout = (const float*)d_in[10];
    float* out = (float*)d_out;

    static bool attr_done = false;
    if (!attr_done) {
        cudaFuncSetAttribute(phase1_mma, cudaFuncAttributeMaxDynamicSharedMemorySize, P1_SMEM);
        cudaFuncSetAttribute(lstm_persistent, cudaFuncAttributeMaxDynamicSharedMemorySize, PS_SMEM);
        attr_done = true;
    }

    pack_x<<<(unsigned)((size_t)Tt * Bb * Ii / 4 / 256), 256>>>(inputs);
    pack_w<<<Ii + Hh, 256>>>(Wf, bf, Wi, bi, Wc, bc, Wo, bo);
    zero_state<<<(Bb * Hh + 255) / 256, 256>>>();

    // Phase 1: M = 131072, N = 2048, K = 256
    phase1_mma<<<dim3(G4 / 128, (Tt * Bb) / 64), 256, P1_SMEM>>>();

    // Persistent recurrence: 32 n-tiles x 4 b-tiles = 128 CTAs, single wave
    lstm_persistent<<<dim3(G4 / 64, Bb / 64), 128, PS_SMEM>>>();

    final_head<<<Bb, 256>>>(Wout, bout, out);
}